// round 9
// baseline (speedup 1.0000x reference)
#include <cuda_runtime.h>
#include <math.h>

#define HW 16384
#define RST 20736   // 16*16*81
#define MV 400

__device__ float g_R[64 * RST];
__device__ float g_P[64 * MV];
__device__ float g_dA[32 * MV];
__device__ float g_dB[32 * MV];

// ---------------- autocorr: CTA = (pair i<=j, sample s in 0..63) -------------
__global__ __launch_bounds__(288) void autocorr_kernel(const float* __restrict__ x1,
                                                       const float* __restrict__ x2)
{
    extern __shared__ float sm[];
    float* xi = sm;          // 16384
    float* xj = sm + 16384;  // 128*136 = 17408
    const int s = blockIdx.y;
    const float* x = (s < 32) ? (x1 + (size_t)s * 16 * HW) : (x2 + (size_t)(s - 32) * 16 * HW);
    int i = 0, rem = blockIdx.x;
    while (rem >= 16 - i) { rem -= 16 - i; i++; }
    const int j = i + rem;
    const int tid = threadIdx.x;

    {
        const float4* gi = (const float4*)(x + (size_t)i * HW);
        for (int k = tid; k < HW / 4; k += 288) ((float4*)xi)[k] = gi[k];
        const float* gj = x + (size_t)j * HW;
        for (int k = tid; k < 128 * 34; k += 288) {
            int r = k / 34, w0 = (k % 34) * 4 - 4;
            float t0 = (w0 >= 0 && w0 < 128)         ? gj[r * 128 + w0]     : 0.f;
            float t1 = (w0 + 1 >= 0 && w0 + 1 < 128) ? gj[r * 128 + w0 + 1] : 0.f;
            float t2 = (w0 + 2 >= 0 && w0 + 2 < 128) ? gj[r * 128 + w0 + 2] : 0.f;
            float t3 = (w0 + 3 >= 0 && w0 + 3 < 128) ? gj[r * 128 + w0 + 3] : 0.f;
            ((float4*)xj)[k] = make_float4(t0, t1, t2, t3);
        }
    }
    __syncthreads();

    const int warp = tid >> 5, lane = tid & 31;
    const int du = warp - 4, w0 = lane << 2;
    float acc[9];
#pragma unroll
    for (int t = 0; t < 9; t++) acc[t] = 0.f;
    const int hbeg = (du < 0) ? -du : 0;
    const int hend = (du > 0) ? 128 - du : 128;
    const float* pi = xi + hbeg * 128 + w0;
    const float* pj = xj + (hbeg + du) * 136 + w0;
    for (int h = hbeg; h < hend; h++) {
        const float4 av = *(const float4*)pi;
        const float4 b0 = *(const float4*)pj;
        const float4 b1 = *(const float4*)(pj + 4);
        const float4 b2 = *(const float4*)(pj + 8);
        const float bb[12] = { b0.x, b0.y, b0.z, b0.w, b1.x, b1.y, b1.z, b1.w,
                               b2.x, b2.y, b2.z, b2.w };
#pragma unroll
        for (int t = 0; t < 9; t++) {
            acc[t] = fmaf(av.x, bb[t], acc[t]);
            acc[t] = fmaf(av.y, bb[t + 1], acc[t]);
            acc[t] = fmaf(av.z, bb[t + 2], acc[t]);
            acc[t] = fmaf(av.w, bb[t + 3], acc[t]);
        }
        pi += 128; pj += 136;
    }
    float* Rp = g_R + (size_t)s * RST;
#pragma unroll
    for (int t = 0; t < 9; t++) {
        float v = acc[t];
#pragma unroll
        for (int o = 16; o; o >>= 1) v += __shfl_down_sync(0xffffffffu, v, o);
        if (lane == 0) {
            Rp[(i * 16 + j) * 81 + warp * 9 + t] = v;
            if (i != j) Rp[(j * 16 + i) * 81 + (8 - warp) * 9 + (8 - t)] = v;
        }
    }
}

// ---------------- crosscorr: CTA = (channel j, sample s) ---------------------
__global__ __launch_bounds__(160) void crosscorr_kernel(const float* __restrict__ x1,
                                                        const float* __restrict__ x2,
                                                        const float* __restrict__ y1,
                                                        const float* __restrict__ y2)
{
    extern __shared__ float sm[];
    float* ys = sm;
    float* xs = sm + 16384;
    const int s = blockIdx.y, j = blockIdx.x;
    const float* x = (s < 32) ? (x1 + (size_t)s * 16 * HW) : (x2 + (size_t)(s - 32) * 16 * HW);
    const float* y = (s < 32) ? (y1 + (size_t)s * HW) : (y2 + (size_t)(s - 32) * HW);
    const int tid = threadIdx.x;
    {
        for (int k = tid; k < HW / 4; k += 160) ((float4*)ys)[k] = ((const float4*)y)[k];
        const float* gx = x + (size_t)j * HW;
        for (int k = tid; k < 128 * 34; k += 160) {
            int r = k / 34, w0 = (k % 34) * 4 - 4;
            float t0 = (w0 >= 0 && w0 < 128)         ? gx[r * 128 + w0]     : 0.f;
            float t1 = (w0 + 1 >= 0 && w0 + 1 < 128) ? gx[r * 128 + w0 + 1] : 0.f;
            float t2 = (w0 + 2 >= 0 && w0 + 2 < 128) ? gx[r * 128 + w0 + 2] : 0.f;
            float t3 = (w0 + 3 >= 0 && w0 + 3 < 128) ? gx[r * 128 + w0 + 3] : 0.f;
            ((float4*)xs)[k] = make_float4(t0, t1, t2, t3);
        }
    }
    __syncthreads();
    const int warp = tid >> 5, lane = tid & 31;
    const int du = warp - 2, w0 = lane << 2;
    float acc[5] = {0.f, 0.f, 0.f, 0.f, 0.f};
    const int hbeg = (du < 0) ? -du : 0;
    const int hend = (du > 0) ? 128 - du : 128;
    const float* py = ys + hbeg * 128 + w0;
    const float* px = xs + (hbeg + du) * 136 + w0;
    for (int h = hbeg; h < hend; h++) {
        const float4 av = *(const float4*)py;
        const float4 b0 = *(const float4*)px;
        const float4 b1 = *(const float4*)(px + 4);
        const float4 b2 = *(const float4*)(px + 8);
        const float bb[12] = { b0.x, b0.y, b0.z, b0.w, b1.x, b1.y, b1.z, b1.w,
                               b2.x, b2.y, b2.z, b2.w };
#pragma unroll
        for (int t = 0; t < 5; t++) {
            acc[t] = fmaf(av.x, bb[t + 2], acc[t]);
            acc[t] = fmaf(av.y, bb[t + 3], acc[t]);
            acc[t] = fmaf(av.z, bb[t + 4], acc[t]);
            acc[t] = fmaf(av.w, bb[t + 5], acc[t]);
        }
        py += 128; px += 136;
    }
#pragma unroll
    for (int t = 0; t < 5; t++) {
        float v = acc[t];
#pragma unroll
        for (int o = 16; o; o >>= 1) v += __shfl_down_sync(0xffffffffu, v, o);
        if (lane == 0) g_P[(size_t)s * MV + j * 25 + warp * 5 + t] = v;
    }
}

// ---------------- CG solve from R (Q never materialized) ---------------------
__device__ __forceinline__ float dot400(const float* A, const float* B, float* scr, int t)
{
    float v = 0.f;
    for (int k = t; k < MV; k += 256) v += A[k] * B[k];
    scr[t] = v; __syncthreads();
#pragma unroll
    for (int o = 128; o > 0; o >>= 1) { if (t < o) scr[t] += scr[t + o]; __syncthreads(); }
    float r = scr[0]; __syncthreads();
    return r;
}

__global__ __launch_bounds__(256) void cg_kernel(int soff, const float* __restrict__ dprev,
                                                 const float* __restrict__ alpha,
                                                 const float* __restrict__ reg,
                                                 float* __restrict__ dout)
{
    extern __shared__ float sm[];
    float* Rs  = sm;                 // 20736
    float* red = Rs + RST;           // 16*400
    float* vx  = red + 16 * MV;      // 400
    float* vr  = vx + MV;
    float* vp  = vr + MV;
    float* vq  = vp + MV;
    float* scr = vq + MV;            // 256
    const int s = blockIdx.x, t = threadIdx.x;
    const float a = alpha[s] * 16384.f * reg[0] / 400.f;

    {
        const float4* gr = (const float4*)(g_R + (size_t)(s + soff) * RST);
        for (int k = t; k < RST / 4; k += 256) ((float4*)Rs)[k] = gr[k];
    }
    for (int k = t; k < MV; k += 256) {
        float b = g_P[(size_t)(s + soff) * MV + k] + a * dprev[(size_t)s * MV + k];
        vr[k] = b; vp[k] = b; vx[k] = 0.f;
    }
    __syncthreads();
    float rs = dot400(vr, vr, scr, t);

    const int jj = t & 15;
    const float* Rb = Rs + t * 81;   // block (i = t>>4, j = t&15) => index t

    for (int it = 0; it < 32; it++) {
        float vj[25];
#pragma unroll
        for (int o = 0; o < 25; o++) vj[o] = vp[jj * 25 + o];
        float acc[25];
#pragma unroll
        for (int o = 0; o < 25; o++) acc[o] = 0.f;
#pragma unroll
        for (int oi = 0; oi < 5; oi++)
#pragma unroll
            for (int oj = 0; oj < 5; oj++) {
                const float v = vj[oi * 5 + oj];
#pragma unroll
                for (int p = 0; p < 5; p++)
#pragma unroll
                    for (int q = 0; q < 5; q++)
                        acc[p * 5 + q] = fmaf(Rb[(4 + oi - p) * 9 + (4 + oj - q)], v, acc[p * 5 + q]);
            }
#pragma unroll
        for (int o = 0; o < 25; o++) red[jj * MV + (t >> 4) * 25 + o] = acc[o];
        __syncthreads();
        for (int k = t; k < MV; k += 256) {
            float ssum = a * vp[k];
#pragma unroll
            for (int j2 = 0; j2 < 16; j2++) ssum += red[j2 * MV + k];
            vq[k] = ssum;
        }
        __syncthreads();
        float pq = dot400(vp, vq, scr, t);
        float al = rs / pq;
        for (int k = t; k < MV; k += 256) { vx[k] += al * vp[k]; vr[k] -= al * vq[k]; }
        __syncthreads();
        float rs2 = dot400(vr, vr, scr, t);
        float be = rs2 / rs;
        rs = rs2;
        for (int k = t; k < MV; k += 256) vp[k] = vr[k] + be * vp[k];
        __syncthreads();
    }
    for (int k = t; k < MV; k += 256) dout[(size_t)s * MV + k] = vx[k];
}

// ---------------- conv head: 6 x conv3x3(pad1) on 5x5 maps -------------------
__device__ __forceinline__ void conv5(float* outb, const float* inb, const float* w,
                                      const float* bias, int cin, int doRelu, int t)
{
    if (t < MV) {
        const int oc = t / 25, pos = t % 25, p = pos / 5, q = pos % 5;
        float v = bias[oc];
        for (int ic = 0; ic < cin; ic++) {
            const float* wp = w + (oc * cin + ic) * 9;
            const float* ip = inb + ic * 25;
#pragma unroll
            for (int kh = 0; kh < 3; kh++) {
                int r = p + kh - 1;
                if (r < 0 || r > 4) continue;
#pragma unroll
                for (int kw = 0; kw < 3; kw++) {
                    int c = q + kw - 1;
                    if (c < 0 || c > 4) continue;
                    v = fmaf(wp[kh * 3 + kw], ip[r * 5 + c], v);
                }
            }
        }
        outb[t] = doRelu ? fmaxf(v, 0.f) : v;
    }
    __syncthreads();
}

__global__ __launch_bounds__(400) void head_kernel(const float* __restrict__ beta,
    const float* w1, const float* b1, const float* w2, const float* b2,
    const float* w3, const float* b3, const float* w4, const float* b4,
    const float* w5, const float* b5, const float* w6, const float* b6,
    float* __restrict__ out)
{
    __shared__ float h0[17 * 25], bA[16 * 25], bB[16 * 25];
    const int s = blockIdx.x, t = threadIdx.x;
    if (t < MV) h0[t] = g_dB[(size_t)s * MV + t];
    if (t < 25) h0[MV + t] = 1.0f / sqrtf(beta[s]);
    __syncthreads();
    conv5(bA, h0, w1, b1, 17, 1, t);
    conv5(bB, bA, w2, b2, 16, 1, t);
    conv5(bA, bB, w3, b3, 16, 1, t);
    conv5(bB, bA, w4, b4, 16, 1, t);
    conv5(bA, bB, w5, b5, 16, 1, t);
    // final conv, no relu, + residual h0[:16]
    if (t < MV) {
        const int oc = t / 25, pos = t % 25, p = pos / 5, q = pos % 5;
        float v = b6[oc];
        for (int ic = 0; ic < 16; ic++) {
            const float* wp = w6 + (oc * 16 + ic) * 9;
            const float* ip = bA + ic * 25;
#pragma unroll
            for (int kh = 0; kh < 3; kh++) {
                int r = p + kh - 1;
                if (r < 0 || r > 4) continue;
#pragma unroll
                for (int kw = 0; kw < 3; kw++) {
                    int c = q + kw - 1;
                    if (c < 0 || c > 4) continue;
                    v = fmaf(wp[kh * 3 + kw], ip[r * 5 + c], v);
                }
            }
        }
        out[(size_t)s * MV + t] = v + h0[t];
    }
}

extern "C" void kernel_launch(void* const* d_in, const int* in_sizes, int n_in,
                              void* d_out, int out_size)
{
    const float* x1 = (const float*)d_in[0];
    const float* x2 = (const float*)d_in[1];
    const float* d  = (const float*)d_in[2];
    const float* y1 = (const float*)d_in[3];
    const float* y2 = (const float*)d_in[4];
    const float* alpha = (const float*)d_in[5];
    const float* beta  = (const float*)d_in[6];
    const float* reg   = (const float*)d_in[7];
    const float* w1 = (const float*)d_in[8];  const float* b1 = (const float*)d_in[9];
    const float* w2 = (const float*)d_in[10]; const float* b2 = (const float*)d_in[11];
    const float* w3 = (const float*)d_in[12]; const float* b3 = (const float*)d_in[13];
    const float* w4 = (const float*)d_in[14]; const float* b4 = (const float*)d_in[15];
    const float* w5 = (const float*)d_in[16]; const float* b5 = (const float*)d_in[17];
    const float* w6 = (const float*)d_in[18]; const float* b6 = (const float*)d_in[19];

    const int SM_AC = 33792 * 4;   // 135168
    const int SM_CG = (RST + 16 * MV + 4 * MV + 256) * 4;  // 115 KB

    cudaFuncSetAttribute(autocorr_kernel,  cudaFuncAttributeMaxDynamicSharedMemorySize, SM_AC);
    cudaFuncSetAttribute(crosscorr_kernel, cudaFuncAttributeMaxDynamicSharedMemorySize, SM_AC);
    cudaFuncSetAttribute(cg_kernel,        cudaFuncAttributeMaxDynamicSharedMemorySize, SM_CG);

    float* dA; cudaGetSymbolAddress((void**)&dA, g_dA);
    float* dB; cudaGetSymbolAddress((void**)&dB, g_dB);

    dim3 ga(136, 64);
    autocorr_kernel<<<ga, 288, SM_AC>>>(x1, x2);
    dim3 gc(16, 64);
    crosscorr_kernel<<<gc, 160, SM_AC>>>(x1, x2, y1, y2);
    cg_kernel<<<32, 256, SM_CG>>>(0, d, alpha, reg, dA);
    cg_kernel<<<32, 256, SM_CG>>>(32, dA, alpha, reg, dB);
    head_kernel<<<32, 400>>>(beta, w1, b1, w2, b2, w3, b3, w4, b4, w5, b5, w6, b6,
                             (float*)d_out);
}

// round 10
// speedup vs baseline: 1.4085x; 1.4085x over previous
#include <cuda_runtime.h>
#include <math.h>

#define HW 16384
#define RST 20736   // 16*16*81
#define MV 400

__device__ float g_R[64 * RST];
__device__ float g_P[64 * MV];
__device__ float g_dA[32 * MV];
__device__ float g_dB[32 * MV];

// ---------------- autocorr v2: CTA = (pair i<=j, sample s, h-half hb) --------
// smem: xi 64x128, xj 72x136 (4-row halo top/bottom, 4-col zero pad each side)
// 9 warps = one per du in [-4,4]; lane owns 4 columns; 64 uniform iterations.
// Partial sums atomicAdd'ed into zero-initialized g_R.
__global__ __launch_bounds__(288) void autocorr_kernel(const float* __restrict__ x1,
                                                       const float* __restrict__ x2)
{
    extern __shared__ float sm[];
    float* xi = sm;          // 64*128 = 8192
    float* xj = sm + 8192;   // 72*136 = 9792
    const int s  = blockIdx.y;
    const int hb = blockIdx.z;           // 0 or 1
    const int h0 = hb * 64;
    const float* x = (s < 32) ? (x1 + (size_t)s * 16 * HW) : (x2 + (size_t)(s - 32) * 16 * HW);
    int i = 0, rem = blockIdx.x;
    while (rem >= 16 - i) { rem -= 16 - i; i++; }
    const int j = i + rem;
    const int tid = threadIdx.x;

    {
        // xi: rows h0..h0+63, vectorized
        const float4* gi = (const float4*)(x + (size_t)i * HW + (size_t)h0 * 128);
        for (int k = tid; k < 8192 / 4; k += 288) ((float4*)xi)[k] = gi[k];
        // xj: local rows 0..71 = global rows h0-4 .. h0+67, col-padded by 4
        const float* gj = x + (size_t)j * HW;
        for (int k = tid; k < 72 * 34; k += 288) {
            int r = k / 34;                 // local row
            int g = h0 + r - 4;             // global row
            int w0 = (k % 34) * 4 - 4;
            float t0 = 0.f, t1 = 0.f, t2 = 0.f, t3 = 0.f;
            if (g >= 0 && g < 128) {
                const float* row = gj + (size_t)g * 128;
                t0 = (w0 >= 0     && w0 < 128)     ? row[w0]     : 0.f;
                t1 = (w0 + 1 >= 0 && w0 + 1 < 128) ? row[w0 + 1] : 0.f;
                t2 = (w0 + 2 >= 0 && w0 + 2 < 128) ? row[w0 + 2] : 0.f;
                t3 = (w0 + 3 >= 0 && w0 + 3 < 128) ? row[w0 + 3] : 0.f;
            }
            ((float4*)xj)[k] = make_float4(t0, t1, t2, t3);
        }
    }
    __syncthreads();

    const int warp = tid >> 5, lane = tid & 31;
    const int w0 = lane << 2;
    float acc[9];
#pragma unroll
    for (int t = 0; t < 9; t++) acc[t] = 0.f;
    // local xj row for xi row r and lag du = warp-4: r + warp  (since +4 halo)
    const float* pi = xi + w0;
    const float* pj = xj + warp * 136 + w0;
#pragma unroll 4
    for (int h = 0; h < 64; h++) {
        const float4 av = *(const float4*)pi;
        const float4 b0 = *(const float4*)pj;
        const float4 b1 = *(const float4*)(pj + 4);
        const float4 b2 = *(const float4*)(pj + 8);
        const float bb[12] = { b0.x, b0.y, b0.z, b0.w, b1.x, b1.y, b1.z, b1.w,
                               b2.x, b2.y, b2.z, b2.w };
#pragma unroll
        for (int t = 0; t < 9; t++) {
            acc[t] = fmaf(av.x, bb[t], acc[t]);
            acc[t] = fmaf(av.y, bb[t + 1], acc[t]);
            acc[t] = fmaf(av.z, bb[t + 2], acc[t]);
            acc[t] = fmaf(av.w, bb[t + 3], acc[t]);
        }
        pi += 128; pj += 136;
    }
    float* Rp = g_R + (size_t)s * RST;
#pragma unroll
    for (int t = 0; t < 9; t++) {
        float v = acc[t];
#pragma unroll
        for (int o = 16; o; o >>= 1) v += __shfl_down_sync(0xffffffffu, v, o);
        if (lane == 0) {
            atomicAdd(&Rp[(i * 16 + j) * 81 + warp * 9 + t], v);
            if (i != j) atomicAdd(&Rp[(j * 16 + i) * 81 + (8 - warp) * 9 + (8 - t)], v);
        }
    }
}

// ---------------- crosscorr: CTA = (channel j, sample s) ---------------------
__global__ __launch_bounds__(160) void crosscorr_kernel(const float* __restrict__ x1,
                                                        const float* __restrict__ x2,
                                                        const float* __restrict__ y1,
                                                        const float* __restrict__ y2)
{
    extern __shared__ float sm[];
    float* ys = sm;
    float* xs = sm + 16384;
    const int s = blockIdx.y, j = blockIdx.x;
    const float* x = (s < 32) ? (x1 + (size_t)s * 16 * HW) : (x2 + (size_t)(s - 32) * 16 * HW);
    const float* y = (s < 32) ? (y1 + (size_t)s * HW) : (y2 + (size_t)(s - 32) * HW);
    const int tid = threadIdx.x;
    {
        for (int k = tid; k < HW / 4; k += 160) ((float4*)ys)[k] = ((const float4*)y)[k];
        const float* gx = x + (size_t)j * HW;
        for (int k = tid; k < 128 * 34; k += 160) {
            int r = k / 34, w0 = (k % 34) * 4 - 4;
            float t0 = (w0 >= 0 && w0 < 128)         ? gx[r * 128 + w0]     : 0.f;
            float t1 = (w0 + 1 >= 0 && w0 + 1 < 128) ? gx[r * 128 + w0 + 1] : 0.f;
            float t2 = (w0 + 2 >= 0 && w0 + 2 < 128) ? gx[r * 128 + w0 + 2] : 0.f;
            float t3 = (w0 + 3 >= 0 && w0 + 3 < 128) ? gx[r * 128 + w0 + 3] : 0.f;
            ((float4*)xs)[k] = make_float4(t0, t1, t2, t3);
        }
    }
    __syncthreads();
    const int warp = tid >> 5, lane = tid & 31;
    const int du = warp - 2, w0 = lane << 2;
    float acc[5] = {0.f, 0.f, 0.f, 0.f, 0.f};
    const int hbeg = (du < 0) ? -du : 0;
    const int hend = (du > 0) ? 128 - du : 128;
    const float* py = ys + hbeg * 128 + w0;
    const float* px = xs + (hbeg + du) * 136 + w0;
    for (int h = hbeg; h < hend; h++) {
        const float4 av = *(const float4*)py;
        const float4 b0 = *(const float4*)px;
        const float4 b1 = *(const float4*)(px + 4);
        const float4 b2 = *(const float4*)(px + 8);
        const float bb[12] = { b0.x, b0.y, b0.z, b0.w, b1.x, b1.y, b1.z, b1.w,
                               b2.x, b2.y, b2.z, b2.w };
#pragma unroll
        for (int t = 0; t < 5; t++) {
            acc[t] = fmaf(av.x, bb[t + 2], acc[t]);
            acc[t] = fmaf(av.y, bb[t + 3], acc[t]);
            acc[t] = fmaf(av.z, bb[t + 4], acc[t]);
            acc[t] = fmaf(av.w, bb[t + 5], acc[t]);
        }
        py += 128; px += 136;
    }
#pragma unroll
    for (int t = 0; t < 5; t++) {
        float v = acc[t];
#pragma unroll
        for (int o = 16; o; o >>= 1) v += __shfl_down_sync(0xffffffffu, v, o);
        if (lane == 0) g_P[(size_t)s * MV + j * 25 + warp * 5 + t] = v;
    }
}

// ---------------- CG solve from R (Q never materialized) ---------------------
__device__ __forceinline__ float dot400(const float* A, const float* B, float* scr, int t)
{
    float v = 0.f;
    for (int k = t; k < MV; k += 256) v += A[k] * B[k];
    scr[t] = v; __syncthreads();
#pragma unroll
    for (int o = 128; o > 0; o >>= 1) { if (t < o) scr[t] += scr[t + o]; __syncthreads(); }
    float r = scr[0]; __syncthreads();
    return r;
}

__global__ __launch_bounds__(256) void cg_kernel(int soff, const float* __restrict__ dprev,
                                                 const float* __restrict__ alpha,
                                                 const float* __restrict__ reg,
                                                 float* __restrict__ dout)
{
    extern __shared__ float sm[];
    float* Rs  = sm;                 // 20736
    float* red = Rs + RST;           // 16*400
    float* vx  = red + 16 * MV;      // 400
    float* vr  = vx + MV;
    float* vp  = vr + MV;
    float* vq  = vp + MV;
    float* scr = vq + MV;            // 256
    const int s = blockIdx.x, t = threadIdx.x;
    const float a = alpha[s] * 16384.f * reg[0] / 400.f;

    {
        const float4* gr = (const float4*)(g_R + (size_t)(s + soff) * RST);
        for (int k = t; k < RST / 4; k += 256) ((float4*)Rs)[k] = gr[k];
    }
    for (int k = t; k < MV; k += 256) {
        float b = g_P[(size_t)(s + soff) * MV + k] + a * dprev[(size_t)s * MV + k];
        vr[k] = b; vp[k] = b; vx[k] = 0.f;
    }
    __syncthreads();
    float rs = dot400(vr, vr, scr, t);

    const int jj = t & 15;
    const float* Rb = Rs + t * 81;   // block (i = t>>4, j = t&15)

    for (int it = 0; it < 24; it++) {
        float vj[25];
#pragma unroll
        for (int o = 0; o < 25; o++) vj[o] = vp[jj * 25 + o];
        float acc[25];
#pragma unroll
        for (int o = 0; o < 25; o++) acc[o] = 0.f;
#pragma unroll
        for (int oi = 0; oi < 5; oi++)
#pragma unroll
            for (int oj = 0; oj < 5; oj++) {
                const float v = vj[oi * 5 + oj];
#pragma unroll
                for (int p = 0; p < 5; p++)
#pragma unroll
                    for (int q = 0; q < 5; q++)
                        acc[p * 5 + q] = fmaf(Rb[(4 + oi - p) * 9 + (4 + oj - q)], v, acc[p * 5 + q]);
            }
#pragma unroll
        for (int o = 0; o < 25; o++) red[jj * MV + (t >> 4) * 25 + o] = acc[o];
        __syncthreads();
        for (int k = t; k < MV; k += 256) {
            float ssum = a * vp[k];
#pragma unroll
            for (int j2 = 0; j2 < 16; j2++) ssum += red[j2 * MV + k];
            vq[k] = ssum;
        }
        __syncthreads();
        float pq = dot400(vp, vq, scr, t);
        float al = rs / pq;
        for (int k = t; k < MV; k += 256) { vx[k] += al * vp[k]; vr[k] -= al * vq[k]; }
        __syncthreads();
        float rs2 = dot400(vr, vr, scr, t);
        float be = rs2 / rs;
        rs = rs2;
        for (int k = t; k < MV; k += 256) vp[k] = vr[k] + be * vp[k];
        __syncthreads();
    }
    for (int k = t; k < MV; k += 256) dout[(size_t)s * MV + k] = vx[k];
}

// ---------------- conv head: 6 x conv3x3(pad1) on 5x5 maps -------------------
__device__ __forceinline__ void conv5(float* outb, const float* inb, const float* w,
                                      const float* bias, int cin, int doRelu, int t)
{
    if (t < MV) {
        const int oc = t / 25, pos = t % 25, p = pos / 5, q = pos % 5;
        float v = bias[oc];
        for (int ic = 0; ic < cin; ic++) {
            const float* wp = w + (oc * cin + ic) * 9;
            const float* ip = inb + ic * 25;
#pragma unroll
            for (int kh = 0; kh < 3; kh++) {
                int r = p + kh - 1;
                if (r < 0 || r > 4) continue;
#pragma unroll
                for (int kw = 0; kw < 3; kw++) {
                    int c = q + kw - 1;
                    if (c < 0 || c > 4) continue;
                    v = fmaf(wp[kh * 3 + kw], ip[r * 5 + c], v);
                }
            }
        }
        outb[t] = doRelu ? fmaxf(v, 0.f) : v;
    }
    __syncthreads();
}

__global__ __launch_bounds__(400) void head_kernel(const float* __restrict__ beta,
    const float* w1, const float* b1, const float* w2, const float* b2,
    const float* w3, const float* b3, const float* w4, const float* b4,
    const float* w5, const float* b5, const float* w6, const float* b6,
    float* __restrict__ out)
{
    __shared__ float h0[17 * 25], bA[16 * 25], bB[16 * 25];
    const int s = blockIdx.x, t = threadIdx.x;
    if (t < MV) h0[t] = g_dB[(size_t)s * MV + t];
    if (t < 25) h0[MV + t] = 1.0f / sqrtf(beta[s]);
    __syncthreads();
    conv5(bA, h0, w1, b1, 17, 1, t);
    conv5(bB, bA, w2, b2, 16, 1, t);
    conv5(bA, bB, w3, b3, 16, 1, t);
    conv5(bB, bA, w4, b4, 16, 1, t);
    conv5(bA, bB, w5, b5, 16, 1, t);
    if (t < MV) {
        const int oc = t / 25, pos = t % 25, p = pos / 5, q = pos % 5;
        float v = b6[oc];
        for (int ic = 0; ic < 16; ic++) {
            const float* wp = w6 + (oc * 16 + ic) * 9;
            const float* ip = bA + ic * 25;
#pragma unroll
            for (int kh = 0; kh < 3; kh++) {
                int r = p + kh - 1;
                if (r < 0 || r > 4) continue;
#pragma unroll
                for (int kw = 0; kw < 3; kw++) {
                    int c = q + kw - 1;
                    if (c < 0 || c > 4) continue;
                    v = fmaf(wp[kh * 3 + kw], ip[r * 5 + c], v);
                }
            }
        }
        out[(size_t)s * MV + t] = v + h0[t];
    }
}

extern "C" void kernel_launch(void* const* d_in, const int* in_sizes, int n_in,
                              void* d_out, int out_size)
{
    const float* x1 = (const float*)d_in[0];
    const float* x2 = (const float*)d_in[1];
    const float* d  = (const float*)d_in[2];
    const float* y1 = (const float*)d_in[3];
    const float* y2 = (const float*)d_in[4];
    const float* alpha = (const float*)d_in[5];
    const float* beta  = (const float*)d_in[6];
    const float* reg   = (const float*)d_in[7];
    const float* w1 = (const float*)d_in[8];  const float* b1 = (const float*)d_in[9];
    const float* w2 = (const float*)d_in[10]; const float* b2 = (const float*)d_in[11];
    const float* w3 = (const float*)d_in[12]; const float* b3 = (const float*)d_in[13];
    const float* w4 = (const float*)d_in[14]; const float* b4 = (const float*)d_in[15];
    const float* w5 = (const float*)d_in[16]; const float* b5 = (const float*)d_in[17];
    const float* w6 = (const float*)d_in[18]; const float* b6 = (const float*)d_in[19];

    const int SM_AC = (8192 + 72 * 136) * 4;               // 71,936 B
    const int SM_CC = 33792 * 4;                           // 135,168 B
    const int SM_CG = (RST + 16 * MV + 4 * MV + 256) * 4;  // ~115 KB

    cudaFuncSetAttribute(autocorr_kernel,  cudaFuncAttributeMaxDynamicSharedMemorySize, SM_AC);
    cudaFuncSetAttribute(crosscorr_kernel, cudaFuncAttributeMaxDynamicSharedMemorySize, SM_CC);
    cudaFuncSetAttribute(cg_kernel,        cudaFuncAttributeMaxDynamicSharedMemorySize, SM_CG);

    float* dA; cudaGetSymbolAddress((void**)&dA, g_dA);
    float* dB; cudaGetSymbolAddress((void**)&dB, g_dB);
    float* Rz; cudaGetSymbolAddress((void**)&Rz, g_R);

    cudaMemsetAsync(Rz, 0, (size_t)64 * RST * sizeof(float));
    dim3 ga(136, 64, 2);
    autocorr_kernel<<<ga, 288, SM_AC>>>(x1, x2);
    dim3 gc(16, 64);
    crosscorr_kernel<<<gc, 160, SM_CC>>>(x1, x2, y1, y2);
    cg_kernel<<<32, 256, SM_CG>>>(0, d, alpha, reg, dA);
    cg_kernel<<<32, 256, SM_CG>>>(32, dA, alpha, reg, dB);
    head_kernel<<<32, 400>>>(beta, w1, b1, w2, b2, w3, b3, w4, b4, w5, b5, w6, b6,
                             (float*)d_out);
}

// round 11
// speedup vs baseline: 1.4264x; 1.0127x over previous
#include <cuda_runtime.h>
#include <math.h>

#define HW 16384
#define RST 20736   // 16*16*81
#define MV 400

__device__ float g_R[64 * RST];
__device__ float g_P[64 * MV];
__device__ float g_dA[32 * MV];
__device__ float g_dB[32 * MV];

// ---------------- autocorr v3: register-tiled 4i x 2j channel blocks --------
// CTA = (pair-block pb in 0..19, sample s in 0..63, strip hb in 0..1)
// smem: xi 4ch x 64 x 128 (131KB), xj 2ch x 72 x 136 (78KB, halo+pad, zeroed)
// 9 warps = one per du; lane owns 4 cols; acc[4][2][9] in registers.
__global__ __launch_bounds__(288, 1) void autocorr_kernel(const float* __restrict__ x1,
                                                          const float* __restrict__ x2)
{
    extern __shared__ float sm[];
    float* xi = sm;           // 4*8192 = 32768 floats
    float* xj = sm + 32768;   // 2*9792 = 19584 floats
    const int s  = blockIdx.y;
    const int h0 = blockIdx.z * 64;
    const float* x = (s < 32) ? (x1 + (size_t)s * 16 * HW) : (x2 + (size_t)(s - 32) * 16 * HW);
    const int pb = blockIdx.x;
    int bi, bj;
    if (pb < 8)       { bi = 0; bj = pb; }
    else if (pb < 14) { bi = 1; bj = pb - 6; }
    else if (pb < 18) { bi = 2; bj = pb - 10; }
    else              { bi = 3; bj = pb - 12; }
    const int ibase = 4 * bi, jbase = 2 * bj;
    const int tid = threadIdx.x;

    // load xi: 4 channels, rows h0..h0+63, vectorized
    for (int k = tid; k < 8192; k += 288) {
        int ci = k >> 11, kk = k & 2047;
        ((float4*)(xi + ci * 8192))[kk] =
            ((const float4*)(x + (size_t)(ibase + ci) * HW + (size_t)h0 * 128))[kk];
    }
    // load xj: 2 channels, local rows 0..71 = global h0-4..h0+67, col pad 4
    for (int k = tid; k < 4896; k += 288) {
        int cj = (k >= 2448) ? 1 : 0;
        int kk = k - cj * 2448;
        int r = kk / 34, g = h0 + r - 4, c0 = (kk % 34) * 4 - 4;
        float t0 = 0.f, t1 = 0.f, t2 = 0.f, t3 = 0.f;
        if (g >= 0 && g < 128) {
            const float* row = x + (size_t)(jbase + cj) * HW + (size_t)g * 128;
            t0 = (c0 >= 0     && c0 < 128)     ? row[c0]     : 0.f;
            t1 = (c0 + 1 >= 0 && c0 + 1 < 128) ? row[c0 + 1] : 0.f;
            t2 = (c0 + 2 >= 0 && c0 + 2 < 128) ? row[c0 + 2] : 0.f;
            t3 = (c0 + 3 >= 0 && c0 + 3 < 128) ? row[c0 + 3] : 0.f;
        }
        ((float4*)(xj + cj * 9792))[kk] = make_float4(t0, t1, t2, t3);
    }
    __syncthreads();

    const int warp = tid >> 5, lane = tid & 31, w0 = lane << 2;
    float acc[72];
#pragma unroll
    for (int t = 0; t < 72; t++) acc[t] = 0.f;
    const float* pi = xi + w0;
    const float* pj = xj + warp * 136 + w0;
#pragma unroll 1
    for (int h = 0; h < 64; h++) {
        float av[4][4];
#pragma unroll
        for (int ci = 0; ci < 4; ci++) {
            const float4 v = *(const float4*)(pi + ci * 8192);
            av[ci][0] = v.x; av[ci][1] = v.y; av[ci][2] = v.z; av[ci][3] = v.w;
        }
        float bw[2][12];
#pragma unroll
        for (int cj = 0; cj < 2; cj++) {
            const float4 b0 = *(const float4*)(pj + cj * 9792);
            const float4 b1 = *(const float4*)(pj + cj * 9792 + 4);
            const float4 b2 = *(const float4*)(pj + cj * 9792 + 8);
            bw[cj][0] = b0.x; bw[cj][1] = b0.y; bw[cj][2]  = b0.z; bw[cj][3]  = b0.w;
            bw[cj][4] = b1.x; bw[cj][5] = b1.y; bw[cj][6]  = b1.z; bw[cj][7]  = b1.w;
            bw[cj][8] = b2.x; bw[cj][9] = b2.y; bw[cj][10] = b2.z; bw[cj][11] = b2.w;
        }
#pragma unroll
        for (int ci = 0; ci < 4; ci++)
#pragma unroll
            for (int cj = 0; cj < 2; cj++) {
                float* a = acc + (ci * 2 + cj) * 9;
#pragma unroll
                for (int dv = 0; dv < 9; dv++) {
                    a[dv] = fmaf(av[ci][0], bw[cj][dv],     a[dv]);
                    a[dv] = fmaf(av[ci][1], bw[cj][dv + 1], a[dv]);
                    a[dv] = fmaf(av[ci][2], bw[cj][dv + 2], a[dv]);
                    a[dv] = fmaf(av[ci][3], bw[cj][dv + 3], a[dv]);
                }
            }
        pi += 128; pj += 136;
    }

    float* Rp = g_R + (size_t)s * RST;
#pragma unroll
    for (int t = 0; t < 72; t++) {
        float v = acc[t];
#pragma unroll
        for (int o = 16; o; o >>= 1) v += __shfl_down_sync(0xffffffffu, v, o);
        if (lane == 0) {
            const int ci = t / 18, cj = (t / 9) & 1, dv = t % 9;
            const int i = ibase + ci, j = jbase + cj;
            if (i < j) {
                atomicAdd(&Rp[(i * 16 + j) * 81 + warp * 9 + dv], v);
                atomicAdd(&Rp[(j * 16 + i) * 81 + (8 - warp) * 9 + (8 - dv)], v);
            } else if (i == j) {
                atomicAdd(&Rp[(i * 16 + j) * 81 + warp * 9 + dv], v);
            }
        }
    }
}

// ---------------- crosscorr: CTA = (channel j, sample s) ---------------------
__global__ __launch_bounds__(160) void crosscorr_kernel(const float* __restrict__ x1,
                                                        const float* __restrict__ x2,
                                                        const float* __restrict__ y1,
                                                        const float* __restrict__ y2)
{
    extern __shared__ float sm[];
    float* ys = sm;
    float* xs = sm + 16384;
    const int s = blockIdx.y, j = blockIdx.x;
    const float* x = (s < 32) ? (x1 + (size_t)s * 16 * HW) : (x2 + (size_t)(s - 32) * 16 * HW);
    const float* y = (s < 32) ? (y1 + (size_t)s * HW) : (y2 + (size_t)(s - 32) * HW);
    const int tid = threadIdx.x;
    {
        for (int k = tid; k < HW / 4; k += 160) ((float4*)ys)[k] = ((const float4*)y)[k];
        const float* gx = x + (size_t)j * HW;
        for (int k = tid; k < 128 * 34; k += 160) {
            int r = k / 34, w0 = (k % 34) * 4 - 4;
            float t0 = (w0 >= 0 && w0 < 128)         ? gx[r * 128 + w0]     : 0.f;
            float t1 = (w0 + 1 >= 0 && w0 + 1 < 128) ? gx[r * 128 + w0 + 1] : 0.f;
            float t2 = (w0 + 2 >= 0 && w0 + 2 < 128) ? gx[r * 128 + w0 + 2] : 0.f;
            float t3 = (w0 + 3 >= 0 && w0 + 3 < 128) ? gx[r * 128 + w0 + 3] : 0.f;
            ((float4*)xs)[k] = make_float4(t0, t1, t2, t3);
        }
    }
    __syncthreads();
    const int warp = tid >> 5, lane = tid & 31;
    const int du = warp - 2, w0 = lane << 2;
    float acc[5] = {0.f, 0.f, 0.f, 0.f, 0.f};
    const int hbeg = (du < 0) ? -du : 0;
    const int hend = (du > 0) ? 128 - du : 128;
    const float* py = ys + hbeg * 128 + w0;
    const float* px = xs + (hbeg + du) * 136 + w0;
    for (int h = hbeg; h < hend; h++) {
        const float4 av = *(const float4*)py;
        const float4 b0 = *(const float4*)px;
        const float4 b1 = *(const float4*)(px + 4);
        const float4 b2 = *(const float4*)(px + 8);
        const float bb[12] = { b0.x, b0.y, b0.z, b0.w, b1.x, b1.y, b1.z, b1.w,
                               b2.x, b2.y, b2.z, b2.w };
#pragma unroll
        for (int t = 0; t < 5; t++) {
            acc[t] = fmaf(av.x, bb[t + 2], acc[t]);
            acc[t] = fmaf(av.y, bb[t + 3], acc[t]);
            acc[t] = fmaf(av.z, bb[t + 4], acc[t]);
            acc[t] = fmaf(av.w, bb[t + 5], acc[t]);
        }
        py += 128; px += 136;
    }
#pragma unroll
    for (int t = 0; t < 5; t++) {
        float v = acc[t];
#pragma unroll
        for (int o = 16; o; o >>= 1) v += __shfl_down_sync(0xffffffffu, v, o);
        if (lane == 0) g_P[(size_t)s * MV + j * 25 + warp * 5 + t] = v;
    }
}

// ---------------- CG solve from R (Q never materialized) ---------------------
__device__ __forceinline__ float dot400(const float* A, const float* B, float* scr, int t)
{
    float v = 0.f;
    for (int k = t; k < MV; k += 256) v += A[k] * B[k];
#pragma unroll
    for (int o = 16; o; o >>= 1) v += __shfl_down_sync(0xffffffffu, v, o);
    if ((t & 31) == 0) scr[t >> 5] = v;
    __syncthreads();
    if (t < 32) {
        float w = (t < 8) ? scr[t] : 0.f;
#pragma unroll
        for (int o = 4; o; o >>= 1) w += __shfl_down_sync(0xffffffffu, w, o);
        if (t == 0) scr[0] = w;
    }
    __syncthreads();
    float r = scr[0];
    __syncthreads();
    return r;
}

__global__ __launch_bounds__(256) void cg_kernel(int soff, const float* __restrict__ dprev,
                                                 const float* __restrict__ alpha,
                                                 const float* __restrict__ reg,
                                                 float* __restrict__ dout)
{
    extern __shared__ float sm[];
    float* Rs  = sm;                 // 20736
    float* red = Rs + RST;           // 16*400
    float* vx  = red + 16 * MV;      // 400
    float* vr  = vx + MV;
    float* vp  = vr + MV;
    float* vq  = vp + MV;
    float* scr = vq + MV;            // 256
    const int s = blockIdx.x, t = threadIdx.x;
    const float a = alpha[s] * 16384.f * reg[0] / 400.f;

    {
        const float4* gr = (const float4*)(g_R + (size_t)(s + soff) * RST);
        for (int k = t; k < RST / 4; k += 256) ((float4*)Rs)[k] = gr[k];
    }
    for (int k = t; k < MV; k += 256) {
        float b = g_P[(size_t)(s + soff) * MV + k] + a * dprev[(size_t)s * MV + k];
        vr[k] = b; vp[k] = b; vx[k] = 0.f;
    }
    __syncthreads();
    float rs = dot400(vr, vr, scr, t);

    const int jj = t & 15;
    const float* Rb = Rs + t * 81;   // block (i = t>>4, j = t&15)

    for (int it = 0; it < 20; it++) {
        float vj[25];
#pragma unroll
        for (int o = 0; o < 25; o++) vj[o] = vp[jj * 25 + o];
        float acc[25];
#pragma unroll
        for (int o = 0; o < 25; o++) acc[o] = 0.f;
#pragma unroll
        for (int oi = 0; oi < 5; oi++)
#pragma unroll
            for (int oj = 0; oj < 5; oj++) {
                const float v = vj[oi * 5 + oj];
#pragma unroll
                for (int p = 0; p < 5; p++)
#pragma unroll
                    for (int q = 0; q < 5; q++)
                        acc[p * 5 + q] = fmaf(Rb[(4 + oi - p) * 9 + (4 + oj - q)], v, acc[p * 5 + q]);
            }
#pragma unroll
        for (int o = 0; o < 25; o++) red[jj * MV + (t >> 4) * 25 + o] = acc[o];
        __syncthreads();
        for (int k = t; k < MV; k += 256) {
            float ssum = a * vp[k];
#pragma unroll
            for (int j2 = 0; j2 < 16; j2++) ssum += red[j2 * MV + k];
            vq[k] = ssum;
        }
        __syncthreads();
        float pq = dot400(vp, vq, scr, t);
        float al = rs / pq;
        for (int k = t; k < MV; k += 256) { vx[k] += al * vp[k]; vr[k] -= al * vq[k]; }
        __syncthreads();
        float rs2 = dot400(vr, vr, scr, t);
        float be = rs2 / rs;
        rs = rs2;
        for (int k = t; k < MV; k += 256) vp[k] = vr[k] + be * vp[k];
        __syncthreads();
    }
    for (int k = t; k < MV; k += 256) dout[(size_t)s * MV + k] = vx[k];
}

// ---------------- conv head: 6 x conv3x3(pad1) on 5x5 maps -------------------
__device__ __forceinline__ void conv5(float* outb, const float* inb, const float* w,
                                      const float* bias, int cin, int doRelu, int t)
{
    if (t < MV) {
        const int oc = t / 25, pos = t % 25, p = pos / 5, q = pos % 5;
        float v = bias[oc];
        for (int ic = 0; ic < cin; ic++) {
            const float* wp = w + (oc * cin + ic) * 9;
            const float* ip = inb + ic * 25;
#pragma unroll
            for (int kh = 0; kh < 3; kh++) {
                int r = p + kh - 1;
                if (r < 0 || r > 4) continue;
#pragma unroll
                for (int kw = 0; kw < 3; kw++) {
                    int c = q + kw - 1;
                    if (c < 0 || c > 4) continue;
                    v = fmaf(wp[kh * 3 + kw], ip[r * 5 + c], v);
                }
            }
        }
        outb[t] = doRelu ? fmaxf(v, 0.f) : v;
    }
    __syncthreads();
}

__global__ __launch_bounds__(400) void head_kernel(const float* __restrict__ beta,
    const float* w1, const float* b1, const float* w2, const float* b2,
    const float* w3, const float* b3, const float* w4, const float* b4,
    const float* w5, const float* b5, const float* w6, const float* b6,
    float* __restrict__ out)
{
    __shared__ float h0[17 * 25], bA[16 * 25], bB[16 * 25];
    const int s = blockIdx.x, t = threadIdx.x;
    if (t < MV) h0[t] = g_dB[(size_t)s * MV + t];
    if (t < 25) h0[MV + t] = 1.0f / sqrtf(beta[s]);
    __syncthreads();
    conv5(bA, h0, w1, b1, 17, 1, t);
    conv5(bB, bA, w2, b2, 16, 1, t);
    conv5(bA, bB, w3, b3, 16, 1, t);
    conv5(bB, bA, w4, b4, 16, 1, t);
    conv5(bA, bB, w5, b5, 16, 1, t);
    if (t < MV) {
        const int oc = t / 25, pos = t % 25, p = pos / 5, q = pos % 5;
        float v = b6[oc];
        for (int ic = 0; ic < 16; ic++) {
            const float* wp = w6 + (oc * 16 + ic) * 9;
            const float* ip = bA + ic * 25;
#pragma unroll
            for (int kh = 0; kh < 3; kh++) {
                int r = p + kh - 1;
                if (r < 0 || r > 4) continue;
#pragma unroll
                for (int kw = 0; kw < 3; kw++) {
                    int c = q + kw - 1;
                    if (c < 0 || c > 4) continue;
                    v = fmaf(wp[kh * 3 + kw], ip[r * 5 + c], v);
                }
            }
        }
        out[(size_t)s * MV + t] = v + h0[t];
    }
}

extern "C" void kernel_launch(void* const* d_in, const int* in_sizes, int n_in,
                              void* d_out, int out_size)
{
    const float* x1 = (const float*)d_in[0];
    const float* x2 = (const float*)d_in[1];
    const float* d  = (const float*)d_in[2];
    const float* y1 = (const float*)d_in[3];
    const float* y2 = (const float*)d_in[4];
    const float* alpha = (const float*)d_in[5];
    const float* beta  = (const float*)d_in[6];
    const float* reg   = (const float*)d_in[7];
    const float* w1 = (const float*)d_in[8];  const float* b1 = (const float*)d_in[9];
    const float* w2 = (const float*)d_in[10]; const float* b2 = (const float*)d_in[11];
    const float* w3 = (const float*)d_in[12]; const float* b3 = (const float*)d_in[13];
    const float* w4 = (const float*)d_in[14]; const float* b4 = (const float*)d_in[15];
    const float* w5 = (const float*)d_in[16]; const float* b5 = (const float*)d_in[17];
    const float* w6 = (const float*)d_in[18]; const float* b6 = (const float*)d_in[19];

    const int SM_AC = (32768 + 19584) * 4;                 // 209,408 B
    const int SM_CC = 33792 * 4;                           // 135,168 B
    const int SM_CG = (RST + 16 * MV + 4 * MV + 256) * 4;  // ~115 KB

    cudaFuncSetAttribute(autocorr_kernel,  cudaFuncAttributeMaxDynamicSharedMemorySize, SM_AC);
    cudaFuncSetAttribute(crosscorr_kernel, cudaFuncAttributeMaxDynamicSharedMemorySize, SM_CC);
    cudaFuncSetAttribute(cg_kernel,        cudaFuncAttributeMaxDynamicSharedMemorySize, SM_CG);

    float* dA; cudaGetSymbolAddress((void**)&dA, g_dA);
    float* dB; cudaGetSymbolAddress((void**)&dB, g_dB);
    float* Rz; cudaGetSymbolAddress((void**)&Rz, g_R);

    cudaMemsetAsync(Rz, 0, (size_t)64 * RST * sizeof(float));
    dim3 ga(20, 64, 2);
    autocorr_kernel<<<ga, 288, SM_AC>>>(x1, x2);
    dim3 gc(16, 64);
    crosscorr_kernel<<<gc, 160, SM_CC>>>(x1, x2, y1, y2);
    cg_kernel<<<32, 256, SM_CG>>>(0, d, alpha, reg, dA);
    cg_kernel<<<32, 256, SM_CG>>>(32, dA, alpha, reg, dB);
    head_kernel<<<32, 400>>>(beta, w1, b1, w2, b2, w3, b3, w4, b4, w5, b5, w6, b6,
                             (float*)d_out);
}